// round 14
// baseline (speedup 1.0000x reference)
#include <cuda_runtime.h>
#include <cuda_fp16.h>
#include <cstdint>
#include <math.h>

// Problem constants
#define BB     8
#define TLEN   2048
#define HIDD   1024
#define NHH    16
#define MDD    16
#define BT     (BB * TLEN)          // 16384 rows
#define N1     (NHH * MDD * MDD)    // 4096
#define K2D    (NHH * MDD * 2)      // 512

// ---------------------------------------------------------------------------
// Scratch (device globals — no allocation allowed)
// ---------------------------------------------------------------------------
__device__ float  g_m[(size_t)BT * N1];               // scan layout [s][t][256] (UNNORMALIZED)
__device__ __half g_ah[(size_t)BT * HIDD];            // hs hi
__device__ __half g_al[(size_t)BT * HIDD];            // hs lo (unscaled)
__device__ __half g_bh[(size_t)N1 * HIDD];            // W_mat^T hi  [n][k]
__device__ __half g_bl[(size_t)N1 * HIDD];            // W_mat^T lo  [n][k]
__device__ __half g_xh[(size_t)BT * K2D];             // scan out hi
__device__ __half g_xl[(size_t)BT * K2D];             // scan out lo
__device__ __half g_wh[(size_t)HIDD * K2D];           // W_out^T hi [n][k]
__device__ __half g_wl[(size_t)HIDD * K2D];           // W_out^T lo [n][k]

// ---------------------------------------------------------------------------
// Helpers
// ---------------------------------------------------------------------------
__device__ __forceinline__ uint32_t smem_u32(const void* p) {
    uint32_t a;
    asm("{ .reg .u64 t; cvta.to.shared.u64 t, %1; cvt.u32.u64 %0, t; }" : "=r"(a) : "l"(p));
    return a;
}
#define CP_ASYNC16(dst, src) \
    asm volatile("cp.async.cg.shared.global [%0], [%1], 16;\n" :: "r"(dst), "l"(src) : "memory")
#define CP_COMMIT()  asm volatile("cp.async.commit_group;\n" ::: "memory")
#define CP_WAITG(n)  asm volatile("cp.async.wait_group %0;\n" :: "n"(n) : "memory")

#define MBAR_INIT(a, c) \
    asm volatile("mbarrier.init.shared.b64 [%0], %1;" :: "r"(a), "r"(c) : "memory")
#define MBAR_ARRIVE(a) \
    asm volatile("mbarrier.arrive.shared.b64 _, [%0];" :: "r"(a) : "memory")
#define MBAR_WAIT(a, ph) do {                                                  \
    uint32_t _m = (a), _p = (ph), _d;                                          \
    asm volatile("{\n\t.reg .pred p;\n\t"                                      \
        "mbarrier.try_wait.parity.acquire.cta.shared::cta.b64 p, [%1], %2;\n\t"\
        "selp.b32 %0, 1, 0, p;\n\t}" : "=r"(_d) : "r"(_m), "r"(_p) : "memory");\
    if (!_d) {                                                                 \
        asm volatile("{\n\t.reg .pred P1;\n\t"                                 \
            "WL_%=:\n\t"                                                       \
            "mbarrier.try_wait.parity.acquire.cta.shared::cta.b64 P1, [%0], %1, 0x989680;\n\t" \
            "@P1 bra.uni WD_%=;\n\t"                                           \
            "bra.uni WL_%=;\n\t"                                               \
            "WD_%=:\n\t}" :: "r"(_m), "r"(_p) : "memory");                     \
    }                                                                          \
} while (0)

__device__ __forceinline__ void ldsm_x4(uint32_t& r0, uint32_t& r1, uint32_t& r2,
                                        uint32_t& r3, uint32_t addr) {
    asm volatile("ldmatrix.sync.aligned.m8n8.x4.shared.b16 {%0,%1,%2,%3}, [%4];"
                 : "=r"(r0), "=r"(r1), "=r"(r2), "=r"(r3) : "r"(addr));
}
__device__ __forceinline__ void mma_f16(float* c, const uint32_t* a, const uint32_t* b) {
    asm volatile(
        "mma.sync.aligned.m16n8k16.row.col.f32.f16.f16.f32 "
        "{%0,%1,%2,%3}, {%4,%5,%6,%7}, {%8,%9}, {%0,%1,%2,%3};"
        : "+f"(c[0]), "+f"(c[1]), "+f"(c[2]), "+f"(c[3])
        : "r"(a[0]), "r"(a[1]), "r"(a[2]), "r"(a[3]), "r"(b[0]), "r"(b[1]));
}
__device__ __forceinline__ uint32_t swz64(uint32_t off) { return off ^ ((off >> 3) & 0x30); } // SW64

__device__ __forceinline__ void split_f16(float a, __half& h, __half& l) {
    h = __float2half_rn(a);
    l = __float2half_rn(a - __half2float(h));
}

// ---------------------------------------------------------------------------
// Conversion kernels
// ---------------------------------------------------------------------------
struct alignas(8) h4 { __half v[4]; };

__global__ __launch_bounds__(256)
void convA_kernel(const float* __restrict__ x, __half* __restrict__ hi,
                  __half* __restrict__ lo)
{
    const int i = blockIdx.x * blockDim.x + threadIdx.x;
    float4 v = ((const float4*)x)[i];
    h4 h, l;
    float a[4] = {v.x, v.y, v.z, v.w};
#pragma unroll
    for (int j = 0; j < 4; j++) split_f16(a[j], h.v[j], l.v[j]);
    ((h4*)hi)[i] = h;
    ((h4*)lo)[i] = l;
}

// Transpose W (KR x NC, row-major) -> [n][k] fp16 hi/lo
__global__ __launch_bounds__(1024)
void convW_kernel(const float* __restrict__ W, __half* __restrict__ wh,
                  __half* __restrict__ wl, int KR, int NC)
{
    __shared__ float tile[32][33];
    const int n_in = blockIdx.x * 32 + threadIdx.x;
    const int k_in = blockIdx.y * 32 + threadIdx.y;
    tile[threadIdx.y][threadIdx.x] = W[(size_t)k_in * NC + n_in];
    __syncthreads();
    const int n_out = blockIdx.x * 32 + threadIdx.y;
    const int k_out = blockIdx.y * 32 + threadIdx.x;
    const float v = tile[threadIdx.x][threadIdx.y];
    __half h, l;
    split_f16(v, h, l);
    const size_t o = (size_t)n_out * KR + k_out;
    wh[o] = h;
    wl[o] = l;
}

// ---------------------------------------------------------------------------
// WARP-SPECIALIZED fused-chunk HMMA GEMM, fp16 2-term split:
//   D = Ah*Bl + Al*Bh + Ah*Bh   [+ bias]
// 384 threads: warps 0-7 = consumers (CTA tile 128x128, 2m x 4n, warp 64x32),
// warps 8-11 = producers (all cp.async). 6-stage x 32KB ring, handoff via
// full/empty mbarriers: full[s] = 128 producer-thread arrivals (after
// wait_group lag-4), empty[s] = 8 consumer-warp arrivals. Consumers run
// free of CTA-wide barriers in the mainloop.
// ---------------------------------------------------------------------------
#define CH_K     32                         // halfs per chunk
#define TILE_B   8192                       // 128 rows * 64 bytes
#define ST_B     (4 * TILE_B)               // 32KB per stage (Ah,Al,Bh,Bl)
#define NSTAGE   6
#define G_SMEM   (1024 + NSTAGE * ST_B)     // ~198KB -> 1 CTA/SM

template <bool PERM, bool GELU, int KDIM, int NDIM>
__global__ __launch_bounds__(384, 1)
void gemm_ws_kernel(const __half* __restrict__ Ah, const __half* __restrict__ Al,
                    const __half* __restrict__ Bh, const __half* __restrict__ Bl,
                    const float* __restrict__ bias, float* __restrict__ C)
{
    constexpr int NCHUNK = KDIM / CH_K;     // 32 (GEMM1) / 16 (GEMM2)

    extern __shared__ char smem[];
    const uint32_t sb = smem_u32(smem);
    const uint32_t tiles = (sb + 1024u + 1023u) & ~1023u;
    const int tid = threadIdx.x;
    const int lane = tid & 31;
    const int bx = blockIdx.x;              // N tile
    const int by = blockIdx.y;              // M tile

    // mbarriers: full[s] at sb+s*16, empty[s] at sb+s*16+8
    if (tid == 0) {
#pragma unroll
        for (int s = 0; s < NSTAGE; s++) {
            MBAR_INIT(sb + s * 16, 128);     // full: producer threads
            MBAR_INIT(sb + s * 16 + 8, 8);   // empty: consumer warps
        }
    }
    __syncthreads();

    if (tid >= 256) {
        // ================= PRODUCER (warps 8-11, 128 threads) ==============
        const int pt  = tid - 256;           // 0..127
        const int row = pt;                  // one 64B row per tile per thread
        const __half* Asrcs[2] = {Ah, Al};
        const __half* Bsrcs[2] = {Bh, Bl};

        for (int c = 0; c < NCHUNK; c++) {
            const int st = c % NSTAGE;
            // wait stage free (first NSTAGE passes immediately via phase=1 trick)
            MBAR_WAIT(sb + st * 16 + 8, ((c / NSTAGE) & 1) ^ 1);

            const uint32_t s = tiles + st * ST_B;
            const int koff = c * CH_K;
#pragma unroll
            for (int a = 0; a < 2; a++) {
                const __half* Ap = Asrcs[a] + (size_t)(by * 128 + row) * KDIM + koff;
                const uint32_t d = s + a * TILE_B;
#pragma unroll
                for (int j = 0; j < 4; j++)
                    CP_ASYNC16(d + swz64(row * 64 + j * 16), Ap + j * 8);
            }
#pragma unroll
            for (int b = 0; b < 2; b++) {
                const __half* Bp = Bsrcs[b] + (size_t)(bx * 128 + row) * KDIM + koff;
                const uint32_t d = s + (2 + b) * TILE_B;
#pragma unroll
                for (int j = 0; j < 4; j++)
                    CP_ASYNC16(d + swz64(row * 64 + j * 16), Bp + j * 8);
            }
            CP_COMMIT();
            if (c >= 4) {
                CP_WAITG(4);                 // chunk c-4's group complete
                MBAR_ARRIVE(sb + ((c - 4) % NSTAGE) * 16);
            }
        }
        // drain tail: chunks NCHUNK-4 .. NCHUNK-1
        CP_WAITG(3); MBAR_ARRIVE(sb + ((NCHUNK - 4) % NSTAGE) * 16);
        CP_WAITG(2); MBAR_ARRIVE(sb + ((NCHUNK - 3) % NSTAGE) * 16);
        CP_WAITG(1); MBAR_ARRIVE(sb + ((NCHUNK - 2) % NSTAGE) * 16);
        CP_WAITG(0); MBAR_ARRIVE(sb + ((NCHUNK - 1) % NSTAGE) * 16);
        return;
    }

    // ==================== CONSUMER (warps 0-7) =============================
    const int warp = tid >> 5;
    const int wm = warp & 1, wn = warp >> 1;

    float acc[4][4][4];
#pragma unroll
    for (int i = 0; i < 4; i++)
#pragma unroll
        for (int j = 0; j < 4; j++)
#pragma unroll
            for (int k = 0; k < 4; k++) acc[i][j][k] = 0.0f;

    const int lrow = lane & 15;
    const int lkof = (lane >> 4) * 16;

    for (int c = 0; c < NCHUNK; c++) {
        const int st = c % NSTAGE;
        MBAR_WAIT(sb + st * 16, (c / NSTAGE) & 1);    // stage data ready

        const uint32_t s   = tiles + st * ST_B;
        const uint32_t a_h = s;
        const uint32_t a_l = s + TILE_B;
        const uint32_t b_h = s + 2 * TILE_B;
        const uint32_t b_l = s + 3 * TILE_B;

#pragma unroll
        for (int ks = 0; ks < 2; ks++) {
            const int kb = ks * 32 + lkof;

            uint32_t bhf[4][2], blf[4][2];
#pragma unroll
            for (int bt = 0; bt < 2; bt++) {
                const int row = wn * 32 + bt * 16 + lrow;
                uint32_t r0, r1, r2, r3;
                ldsm_x4(r0, r1, r2, r3, b_l + swz64(row * 64 + kb));
                blf[bt * 2 + 0][0] = r0; blf[bt * 2 + 1][0] = r1;
                blf[bt * 2 + 0][1] = r2; blf[bt * 2 + 1][1] = r3;
                ldsm_x4(r0, r1, r2, r3, b_h + swz64(row * 64 + kb));
                bhf[bt * 2 + 0][0] = r0; bhf[bt * 2 + 1][0] = r1;
                bhf[bt * 2 + 0][1] = r2; bhf[bt * 2 + 1][1] = r3;
            }

#pragma unroll
            for (int mt = 0; mt < 4; mt++) {
                const int row = wm * 64 + mt * 16 + lrow;
                uint32_t ahf[4], alf[4];
                ldsm_x4(ahf[0], ahf[1], ahf[2], ahf[3],
                        a_h + swz64(row * 64 + kb));
                ldsm_x4(alf[0], alf[1], alf[2], alf[3],
                        a_l + swz64(row * 64 + kb));
#pragma unroll
                for (int nt = 0; nt < 4; nt++)
                    mma_f16(acc[mt][nt], ahf, blf[nt]);
#pragma unroll
                for (int nt = 0; nt < 4; nt++)
                    mma_f16(acc[mt][nt], alf, bhf[nt]);
#pragma unroll
                for (int nt = 0; nt < 4; nt++)
                    mma_f16(acc[mt][nt], ahf, bhf[nt]);
            }
        }
        if (lane == 0) MBAR_ARRIVE(sb + st * 16 + 8); // stage consumed
    }

    // ---- epilogue (consumers only) ----
    const int g = lane >> 2, t4 = lane & 3;
#pragma unroll
    for (int mt = 0; mt < 4; mt++) {
#pragma unroll
        for (int nt = 0; nt < 4; nt++) {
            const int rm = by * 128 + wm * 64 + mt * 16 + g;
            const int cg = bx * 128 + wn * 32 + nt * 8 + t4 * 2;
            const float b0 = __ldg(&bias[cg]);
            const float b1 = __ldg(&bias[cg + 1]);
            float v0 = acc[mt][nt][0] + b0;
            float v1 = acc[mt][nt][1] + b1;
            float v2 = acc[mt][nt][2] + b0;
            float v3 = acc[mt][nt][3] + b1;
            if (GELU) {
                v0 = 0.5f * v0 * (1.0f + erff(v0 * 0.70710678118654752f));
                v1 = 0.5f * v1 * (1.0f + erff(v1 * 0.70710678118654752f));
                v2 = 0.5f * v2 * (1.0f + erff(v2 * 0.70710678118654752f));
                v3 = 0.5f * v3 * (1.0f + erff(v3 * 0.70710678118654752f));
            }
            if (PERM) {
                const int nh = cg >> 8, ij = cg & 255;
                const int b_ = rm >> 11, t_ = rm & (TLEN - 1);
                float* o = C + (((size_t)(b_ * 16 + nh) * TLEN + t_) * 256 + ij);
                *(float2*)o = make_float2(v0, v1);
                *(float2*)(o + 8 * 256) = make_float2(v2, v3);
            } else {
                float* o = C + ((size_t)rm * NDIM + cg);
                *(float2*)o = make_float2(v0, v1);
                *(float2*)(o + (size_t)8 * NDIM) = make_float2(v2, v3);
            }
        }
    }
}

// ---------------------------------------------------------------------------
// Sequential scan on UNNORMALIZED matrices (scale-invariant), deep register
// prefetch (ring of 8, MLP=8), deferred vector normalization (rescale /4).
// ---------------------------------------------------------------------------
#define PF 8

__global__ __launch_bounds__(32)
void scan_kernel(const float* __restrict__ mn, __half* __restrict__ xh,
                 __half* __restrict__ xl)
{
    const unsigned F = 0xffffffffu;
    const int lane = threadIdx.x & 31;
    const int s = blockIdx.x & 127;
    const int d = blockIdx.x >> 7;
    const int b = s >> 4;
    const int nh = s & 15;

    const int laneoff = (lane & 15) * 16 + (lane >> 4) * 8;
    const float* base = mn + (size_t)s * (TLEN * 256) + laneoff;
    const int h8 = (lane >> 4) << 3;

    const int t0 = d ? (TLEN - 1) : 0;
    const int dt = d ? -1 : 1;

    float u = ((lane & 15) == 0) ? 1.0f : 0.0f;
    const size_t xoff = (size_t)b * TLEN * 512 + nh * 32 + d * 16 + (lane & 15);

    float4 r0[PF], r1[PF];
#pragma unroll
    for (int j = 0; j < PF; j++) {
        const int tj = t0 + j * dt;
        const float* q = base + (size_t)tj * 256;
        r0[j] = __ldg((const float4*)q);
        r1[j] = __ldg((const float4*)(q + 4));
    }

#pragma unroll 1
    for (int blk = 0; blk < TLEN / PF; ++blk) {
#pragma unroll
        for (int sub = 0; sub < PF; ++sub) {
            const int step = blk * PF + sub;
            const int t = t0 + step * dt;

            const float4 c0 = r0[sub];
            const float4 c1 = r1[sub];

            int tp = t + PF * dt;
            tp = tp < 0 ? 0 : (tp > TLEN - 1 ? TLEN - 1 : tp);
            const float* q = base + (size_t)tp * 256;
            r0[sub] = __ldg((const float4*)q);
            r1[sub] = __ldg((const float4*)(q + 4));

            const float vb0 = __shfl_sync(F, u, h8 + 0);
            const float vb1 = __shfl_sync(F, u, h8 + 1);
            const float vb2 = __shfl_sync(F, u, h8 + 2);
            const float vb3 = __shfl_sync(F, u, h8 + 3);
            const float vb4 = __shfl_sync(F, u, h8 + 4);
            const float vb5 = __shfl_sync(F, u, h8 + 5);
            const float vb6 = __shfl_sync(F, u, h8 + 6);
            const float vb7 = __shfl_sync(F, u, h8 + 7);

            float pA = c0.x * vb0;
            pA = fmaf(c0.y, vb1, pA);
            pA = fmaf(c0.z, vb2, pA);
            pA = fmaf(c0.w, vb3, pA);
            float pB = c1.x * vb4;
            pB = fmaf(c1.y, vb5, pB);
            pB = fmaf(c1.z, vb6, pB);
            pB = fmaf(c1.w, vb7, pB);
            const float pp = pA + pB;

            const float nv = pp + __shfl_xor_sync(F, pp, 16);

            float ss = nv * nv;
            ss += __shfl_xor_sync(F, ss, 8);
            ss += __shfl_xor_sync(F, ss, 4);
            ss += __shfl_xor_sync(F, ss, 2);
            ss += __shfl_xor_sync(F, ss, 1);
            const float w = nv / (sqrtf(ss) + 1e-6f);

            if (lane < 16) {
                __half h, l;
                split_f16(w, h, l);
                xh[xoff + (size_t)t * 512] = h;
                xl[xoff + (size_t)t * 512] = l;
            }

            u = ((sub & 3) == 3) ? w : nv;
        }
    }
}

// ---------------------------------------------------------------------------
// Launch
// ---------------------------------------------------------------------------
extern "C" void kernel_launch(void* const* d_in, const int* in_sizes, int n_in,
                              void* d_out, int out_size)
{
    const float* hs = (const float*)d_in[0];
    const float* Wm = (const float*)d_in[1];
    const float* bm = (const float*)d_in[2];
    const float* Wo = (const float*)d_in[3];
    const float* bo = (const float*)d_in[4];
    float* out = (float*)d_out;

    float* pm;
    __half *pah, *pal, *pbh, *pbl, *pxh, *pxl, *pwh, *pwl;
    cudaGetSymbolAddress((void**)&pm, g_m);
    cudaGetSymbolAddress((void**)&pah, g_ah);
    cudaGetSymbolAddress((void**)&pal, g_al);
    cudaGetSymbolAddress((void**)&pbh, g_bh);
    cudaGetSymbolAddress((void**)&pbl, g_bl);
    cudaGetSymbolAddress((void**)&pxh, g_xh);
    cudaGetSymbolAddress((void**)&pxl, g_xl);
    cudaGetSymbolAddress((void**)&pwh, g_wh);
    cudaGetSymbolAddress((void**)&pwl, g_wl);

    // 0) fp16 splits
    convA_kernel<<<(BT * HIDD / 4) / 256, 256>>>(hs, pah, pal);
    convW_kernel<<<dim3(N1 / 32, HIDD / 32), dim3(32, 32)>>>(Wm, pbh, pbl, HIDD, N1);
    convW_kernel<<<dim3(HIDD / 32, K2D / 32), dim3(32, 32)>>>(Wo, pwh, pwl, K2D, HIDD);

    // 1) GEMM1 warp-specialized -> scan layout (+bias), unnormalized
    cudaFuncSetAttribute(gemm_ws_kernel<true, false, HIDD, N1>,
                         cudaFuncAttributeMaxDynamicSharedMemorySize, G_SMEM);
    gemm_ws_kernel<true, false, HIDD, N1>
        <<<dim3(N1 / 128, BT / 128), 384, G_SMEM>>>(pah, pal, pbh, pbl, bm, pm);

    // 2) Bidirectional scan (scale-invariant; no fro-norm) -> fp16 hi/lo
    scan_kernel<<<256, 32>>>(pm, pxh, pxl);

    // 3) GEMM2 warp-specialized: out = gelu(x @ W_out + b_out)
    cudaFuncSetAttribute(gemm_ws_kernel<false, true, K2D, HIDD>,
                         cudaFuncAttributeMaxDynamicSharedMemorySize, G_SMEM);
    gemm_ws_kernel<false, true, K2D, HIDD>
        <<<dim3(HIDD / 128, BT / 128), 384, G_SMEM>>>(pxh, pxl, pwh, pwl, bo, out);
}

// round 15
// speedup vs baseline: 1.4588x; 1.4588x over previous
#include <cuda_runtime.h>
#include <cuda_fp16.h>
#include <cstdint>
#include <math.h>

// Problem constants
#define BB     8
#define TLEN   2048
#define HIDD   1024
#define NHH    16
#define MDD    16
#define BT     (BB * TLEN)          // 16384 rows
#define N1     (NHH * MDD * MDD)    // 4096
#define K2D    (NHH * MDD * 2)      // 512

// ---------------------------------------------------------------------------
// Scratch (device globals — no allocation allowed)
// ---------------------------------------------------------------------------
__device__ float  g_m[(size_t)BT * N1];               // scan layout [s][t][256] (UNNORMALIZED)
__device__ __half g_ah[(size_t)BT * HIDD];            // hs hi
__device__ __half g_al[(size_t)BT * HIDD];            // hs lo (unscaled)
__device__ __half g_bh[(size_t)N1 * HIDD];            // W_mat^T hi  [n][k]
__device__ __half g_bl[(size_t)N1 * HIDD];            // W_mat^T lo  [n][k]
__device__ __half g_xh[(size_t)BT * K2D];             // scan out hi
__device__ __half g_xl[(size_t)BT * K2D];             // scan out lo
__device__ __half g_wh[(size_t)HIDD * K2D];           // W_out^T hi [n][k]
__device__ __half g_wl[(size_t)HIDD * K2D];           // W_out^T lo [n][k]

// ---------------------------------------------------------------------------
// Helpers
// ---------------------------------------------------------------------------
__device__ __forceinline__ uint32_t smem_u32(const void* p) {
    uint32_t a;
    asm("{ .reg .u64 t; cvta.to.shared.u64 t, %1; cvt.u32.u64 %0, t; }" : "=r"(a) : "l"(p));
    return a;
}
#define CP_ASYNC16(dst, src) \
    asm volatile("cp.async.cg.shared.global [%0], [%1], 16;\n" :: "r"(dst), "l"(src) : "memory")
#define CP_COMMIT()  asm volatile("cp.async.commit_group;\n" ::: "memory")
#define CP_WAIT1()   asm volatile("cp.async.wait_group 1;\n" ::: "memory")
#define CP_WAIT11()  asm volatile("cp.async.wait_group 11;\n" ::: "memory")

__device__ __forceinline__ void ldsm_x4(uint32_t& r0, uint32_t& r1, uint32_t& r2,
                                        uint32_t& r3, uint32_t addr) {
    asm volatile("ldmatrix.sync.aligned.m8n8.x4.shared.b16 {%0,%1,%2,%3}, [%4];"
                 : "=r"(r0), "=r"(r1), "=r"(r2), "=r"(r3) : "r"(addr));
}
__device__ __forceinline__ void mma_f16(float* c, const uint32_t* a, const uint32_t* b) {
    asm volatile(
        "mma.sync.aligned.m16n8k16.row.col.f32.f16.f16.f32 "
        "{%0,%1,%2,%3}, {%4,%5,%6,%7}, {%8,%9}, {%0,%1,%2,%3};"
        : "+f"(c[0]), "+f"(c[1]), "+f"(c[2]), "+f"(c[3])
        : "r"(a[0]), "r"(a[1]), "r"(a[2]), "r"(a[3]), "r"(b[0]), "r"(b[1]));
}
__device__ __forceinline__ uint32_t swz64(uint32_t off) { return off ^ ((off >> 3) & 0x30); } // SW64

__device__ __forceinline__ void split_f16(float a, __half& h, __half& l) {
    h = __float2half_rn(a);
    l = __float2half_rn(a - __half2float(h));
}

// ---------------------------------------------------------------------------
// Conversion kernels
// ---------------------------------------------------------------------------
struct alignas(8) h4 { __half v[4]; };

__global__ __launch_bounds__(256)
void convA_kernel(const float* __restrict__ x, __half* __restrict__ hi,
                  __half* __restrict__ lo)
{
    const int i = blockIdx.x * blockDim.x + threadIdx.x;
    float4 v = ((const float4*)x)[i];
    h4 h, l;
    float a[4] = {v.x, v.y, v.z, v.w};
#pragma unroll
    for (int j = 0; j < 4; j++) split_f16(a[j], h.v[j], l.v[j]);
    ((h4*)hi)[i] = h;
    ((h4*)lo)[i] = l;
}

// Transpose W (KR x NC, row-major) -> [n][k] fp16 hi/lo
__global__ __launch_bounds__(1024)
void convW_kernel(const float* __restrict__ W, __half* __restrict__ wh,
                  __half* __restrict__ wl, int KR, int NC)
{
    __shared__ float tile[32][33];
    const int n_in = blockIdx.x * 32 + threadIdx.x;
    const int k_in = blockIdx.y * 32 + threadIdx.y;
    tile[threadIdx.y][threadIdx.x] = W[(size_t)k_in * NC + n_in];
    __syncthreads();
    const int n_out = blockIdx.x * 32 + threadIdx.y;
    const int k_out = blockIdx.y * 32 + threadIdx.x;
    const float v = tile[threadIdx.x][threadIdx.y];
    __half h, l;
    split_f16(v, h, l);
    const size_t o = (size_t)n_out * KR + k_out;
    wh[o] = h;
    wl[o] = l;
}

// ---------------------------------------------------------------------------
// FUSED-CHUNK HMMA GEMM (R13 baseline — best known):
//   D = Ah*Bl + Al*Bh + Ah*Bh   [+ bias]
// CTA 128x128, 8 warps (2m x 4n), SW64 swizzle, 3-stage ring, 2 CTAs/SM.
// ---------------------------------------------------------------------------
#define CH_K     32                         // halfs per chunk
#define TILE_B   8192                       // 128 rows * 64 bytes
#define ST_B     (4 * TILE_B)               // 32KB per stage (Ah,Al,Bh,Bl)
#define G_SMEM   (1024 + 3 * ST_B)

template <bool PERM, bool GELU, int KDIM, int NDIM>
__global__ __launch_bounds__(256, 2)
void gemm_fused_kernel(const __half* __restrict__ Ah, const __half* __restrict__ Al,
                       const __half* __restrict__ Bh, const __half* __restrict__ Bl,
                       const float* __restrict__ bias, float* __restrict__ C)
{
    constexpr int NCHUNK = KDIM / CH_K;

    extern __shared__ char smem[];
    const uint32_t tiles = (smem_u32(smem) + 1023u) & ~1023u;
    const int tid = threadIdx.x;
    const int lane = tid & 31, warp = tid >> 5;
    const int wm = warp & 1, wn = warp >> 1;     // 2 x 4 warp grid
    const int bx = blockIdx.x;                   // N tile
    const int by = blockIdx.y;                   // M tile

    const int lr  = tid >> 2;          // 0..63 (row)
    const int lcb = (tid & 3) * 16;    // byte col within 64B row

    const __half* Asrcs[2] = {Ah, Al};
    const __half* Bsrcs[2] = {Bh, Bl};

    auto issue_loads = [&](int chunk) {
        const int stage = chunk % 3;
        const uint32_t s = tiles + stage * ST_B;
        const int koff = chunk * CH_K + (lcb >> 1);
#pragma unroll
        for (int a = 0; a < 2; a++) {
            const __half* Ap = Asrcs[a] + (size_t)(by * 128 + lr) * KDIM + koff;
            const uint32_t d = s + a * TILE_B;
            CP_ASYNC16(d + swz64(lr * 64 + lcb), Ap);
            CP_ASYNC16(d + swz64((lr + 64) * 64 + lcb), Ap + (size_t)64 * KDIM);
        }
#pragma unroll
        for (int b = 0; b < 2; b++) {
            const __half* Bp = Bsrcs[b] + (size_t)(bx * 128 + lr) * KDIM + koff;
            const uint32_t d = s + (2 + b) * TILE_B;
            CP_ASYNC16(d + swz64(lr * 64 + lcb), Bp);
            CP_ASYNC16(d + swz64((lr + 64) * 64 + lcb), Bp + (size_t)64 * KDIM);
        }
    };

    float acc[4][4][4];
#pragma unroll
    for (int i = 0; i < 4; i++)
#pragma unroll
        for (int j = 0; j < 4; j++)
#pragma unroll
            for (int k = 0; k < 4; k++) acc[i][j][k] = 0.0f;

    const int lrow = lane & 15;
    const int lkof = (lane >> 4) * 16;

    issue_loads(0); CP_COMMIT();
    issue_loads(1); CP_COMMIT();

    for (int i = 0; i < NCHUNK; i++) {
        CP_WAIT1();
        __syncthreads();
        if (i + 2 < NCHUNK) issue_loads(i + 2);
        CP_COMMIT();

        const uint32_t s   = tiles + (i % 3) * ST_B;
        const uint32_t a_h = s;
        const uint32_t a_l = s + TILE_B;
        const uint32_t b_h = s + 2 * TILE_B;
        const uint32_t b_l = s + 3 * TILE_B;

#pragma unroll
        for (int ks = 0; ks < 2; ks++) {
            const int kb = ks * 32 + lkof;

            uint32_t bhf[4][2], blf[4][2];
#pragma unroll
            for (int bt = 0; bt < 2; bt++) {
                const int row = wn * 32 + bt * 16 + lrow;
                uint32_t r0, r1, r2, r3;
                ldsm_x4(r0, r1, r2, r3, b_l + swz64(row * 64 + kb));
                blf[bt * 2 + 0][0] = r0; blf[bt * 2 + 1][0] = r1;
                blf[bt * 2 + 0][1] = r2; blf[bt * 2 + 1][1] = r3;
                ldsm_x4(r0, r1, r2, r3, b_h + swz64(row * 64 + kb));
                bhf[bt * 2 + 0][0] = r0; bhf[bt * 2 + 1][0] = r1;
                bhf[bt * 2 + 0][1] = r2; bhf[bt * 2 + 1][1] = r3;
            }

#pragma unroll
            for (int mt = 0; mt < 4; mt++) {
                const int row = wm * 64 + mt * 16 + lrow;
                uint32_t ahf[4], alf[4];
                ldsm_x4(ahf[0], ahf[1], ahf[2], ahf[3],
                        a_h + swz64(row * 64 + kb));
                ldsm_x4(alf[0], alf[1], alf[2], alf[3],
                        a_l + swz64(row * 64 + kb));
#pragma unroll
                for (int nt = 0; nt < 4; nt++)
                    mma_f16(acc[mt][nt], ahf, blf[nt]);
#pragma unroll
                for (int nt = 0; nt < 4; nt++)
                    mma_f16(acc[mt][nt], alf, bhf[nt]);
#pragma unroll
                for (int nt = 0; nt < 4; nt++)
                    mma_f16(acc[mt][nt], ahf, bhf[nt]);
            }
        }
    }

    // ---- epilogue ----
    const int g = lane >> 2, t4 = lane & 3;
#pragma unroll
    for (int mt = 0; mt < 4; mt++) {
#pragma unroll
        for (int nt = 0; nt < 4; nt++) {
            const int rm = by * 128 + wm * 64 + mt * 16 + g;
            const int cg = bx * 128 + wn * 32 + nt * 8 + t4 * 2;
            const float b0 = __ldg(&bias[cg]);
            const float b1 = __ldg(&bias[cg + 1]);
            float v0 = acc[mt][nt][0] + b0;
            float v1 = acc[mt][nt][1] + b1;
            float v2 = acc[mt][nt][2] + b0;
            float v3 = acc[mt][nt][3] + b1;
            if (GELU) {
                v0 = 0.5f * v0 * (1.0f + erff(v0 * 0.70710678118654752f));
                v1 = 0.5f * v1 * (1.0f + erff(v1 * 0.70710678118654752f));
                v2 = 0.5f * v2 * (1.0f + erff(v2 * 0.70710678118654752f));
                v3 = 0.5f * v3 * (1.0f + erff(v3 * 0.70710678118654752f));
            }
            if (PERM) {
                const int nh = cg >> 8, ij = cg & 255;
                const int b_ = rm >> 11, t_ = rm & (TLEN - 1);
                float* o = C + (((size_t)(b_ * 16 + nh) * TLEN + t_) * 256 + ij);
                *(float2*)o = make_float2(v0, v1);
                *(float2*)(o + 8 * 256) = make_float2(v2, v3);
            } else {
                float* o = C + ((size_t)rm * NDIM + cg);
                *(float2*)o = make_float2(v0, v1);
                *(float2*)(o + (size_t)8 * NDIM) = make_float2(v2, v3);
            }
        }
    }
}

// ---------------------------------------------------------------------------
// Scan v2: cp.async SMEM RING (12 slots x 1KB), one commit group per step,
// wait_group 11 => exact 12-step prefetch distance, no register-ring pressure.
// Lane mapping is LANE-LOCAL: lane l copies matrix bytes [l*32, l*32+32) and
// reads the same bytes back (XOR-16 swizzle on l&4 kills LDS.128 bank
// conflicts). Lane l holds row (l>>1), column half (l&1); row partials are
// pair-combined with shfl_xor(.,1). Deferred normalization (rescale every
// 4th step). One warp per (sequence, direction). Grid 256 x 32 threads.
// ---------------------------------------------------------------------------
#define SDEPTH 12

__global__ __launch_bounds__(32)
void scan_kernel(const float* __restrict__ mn, __half* __restrict__ xh,
                 __half* __restrict__ xl)
{
    __shared__ __align__(16) char ring[SDEPTH * 1024];

    const unsigned F = 0xffffffffu;
    const int lane = threadIdx.x & 31;
    const int s = blockIdx.x & 127;        // sequence (b*16+nh)
    const int d = blockIdx.x >> 7;         // 0 = lr, 1 = rl
    const int b = s >> 4;
    const int nh = s & 15;

    const uint32_t rb = smem_u32(ring);
    // lane-local 32B slice of each matrix; XOR-16 swizzle on lanes with bit2
    const uint32_t sw = (lane & 4) << 2;                 // 0 or 16
    const uint32_t o0 = ((uint32_t)lane * 32) ^ sw;
    const uint32_t o1 = ((uint32_t)lane * 32 + 16) ^ sw;

    const float* base = mn + (size_t)s * (TLEN * 256) + lane * 8;

    const int t0 = d ? (TLEN - 1) : 0;
    const int dt = d ? -1 : 1;

    // lane l: row = l>>1, column half h = l&1 (cols h*8 .. h*8+7)
    const int h16 = (lane & 1) << 4;       // shfl source base = 2*(h*8)

    float u = (lane < 2) ? 1.0f : 0.0f;    // v0 = e0, row 0 pair
    const size_t xoff = (size_t)b * TLEN * 512 + nh * 32 + d * 16 + (lane >> 1);

    // prologue: fill 12 slots (one commit group each)
#pragma unroll
    for (int j = 0; j < SDEPTH; j++) {
        const float* q = base + (size_t)(t0 + j * dt) * 256;
        CP_ASYNC16(rb + j * 1024 + o0, q);
        CP_ASYNC16(rb + j * 1024 + o1, q + 4);
        CP_COMMIT();
    }

    int slot = 0;
#pragma unroll 1
    for (int blk = 0; blk < TLEN / 4; ++blk) {
#pragma unroll
        for (int sub = 0; sub < 4; ++sub) {
            const int step = blk * 4 + sub;
            const int t = t0 + step * dt;

            CP_WAIT11();                       // slot's group complete

            const float4 c0 = *(const float4*)(ring + slot * 1024 + o0);
            const float4 c1 = *(const float4*)(ring + slot * 1024 + o1);

            // prefetch step+SDEPTH into this slot (clamped near the end)
            int tp = t + SDEPTH * dt;
            tp = tp < 0 ? 0 : (tp > TLEN - 1 ? TLEN - 1 : tp);
            const float* q = base + (size_t)tp * 256;
            CP_ASYNC16(rb + slot * 1024 + o0, q);
            CP_ASYNC16(rb + slot * 1024 + o1, q + 4);
            CP_COMMIT();

            // broadcast v[h*8 + k] (v[c] lives in lanes 2c, 2c+1)
            const float vb0 = __shfl_sync(F, u, h16 + 0);
            const float vb1 = __shfl_sync(F, u, h16 + 2);
            const float vb2 = __shfl_sync(F, u, h16 + 4);
            const float vb3 = __shfl_sync(F, u, h16 + 6);
            const float vb4 = __shfl_sync(F, u, h16 + 8);
            const float vb5 = __shfl_sync(F, u, h16 + 10);
            const float vb6 = __shfl_sync(F, u, h16 + 12);
            const float vb7 = __shfl_sync(F, u, h16 + 14);

            float pA = c0.x * vb0;
            pA = fmaf(c0.y, vb1, pA);
            pA = fmaf(c0.z, vb2, pA);
            pA = fmaf(c0.w, vb3, pA);
            float pB = c1.x * vb4;
            pB = fmaf(c1.y, vb5, pB);
            pB = fmaf(c1.z, vb6, pB);
            pB = fmaf(c1.w, vb7, pB);
            const float pp = pA + pB;

            // combine column halves (lanes 2r, 2r+1 both get row r's nv)
            const float nv = pp + __shfl_xor_sync(F, pp, 1);

            // squared norm over the 16 distinct rows (pairs deduped by
            // reducing only over bits 1..4)
            float ss = nv * nv;
            ss += __shfl_xor_sync(F, ss, 2);
            ss += __shfl_xor_sync(F, ss, 4);
            ss += __shfl_xor_sync(F, ss, 8);
            ss += __shfl_xor_sync(F, ss, 16);
            const float w = nv / (sqrtf(ss) + 1e-6f);

            if ((lane & 1) == 0) {
                __half h, l;
                split_f16(w, h, l);
                xh[xoff + (size_t)t * 512] = h;
                xl[xoff + (size_t)t * 512] = l;
            }

            // rescale every 4th step; other steps carry unnormalized nv
            u = (sub == 3) ? w : nv;

            if (++slot == SDEPTH) slot = 0;
        }
    }
}

// ---------------------------------------------------------------------------
// Launch
// ---------------------------------------------------------------------------
extern "C" void kernel_launch(void* const* d_in, const int* in_sizes, int n_in,
                              void* d_out, int out_size)
{
    const float* hs = (const float*)d_in[0];
    const float* Wm = (const float*)d_in[1];
    const float* bm = (const float*)d_in[2];
    const float* Wo = (const float*)d_in[3];
    const float* bo = (const float*)d_in[4];
    float* out = (float*)d_out;

    float* pm;
    __half *pah, *pal, *pbh, *pbl, *pxh, *pxl, *pwh, *pwl;
    cudaGetSymbolAddress((void**)&pm, g_m);
    cudaGetSymbolAddress((void**)&pah, g_ah);
    cudaGetSymbolAddress((void**)&pal, g_al);
    cudaGetSymbolAddress((void**)&pbh, g_bh);
    cudaGetSymbolAddress((void**)&pbl, g_bl);
    cudaGetSymbolAddress((void**)&pxh, g_xh);
    cudaGetSymbolAddress((void**)&pxl, g_xl);
    cudaGetSymbolAddress((void**)&pwh, g_wh);
    cudaGetSymbolAddress((void**)&pwl, g_wl);

    // 0) fp16 splits
    convA_kernel<<<(BT * HIDD / 4) / 256, 256>>>(hs, pah, pal);
    convW_kernel<<<dim3(N1 / 32, HIDD / 32), dim3(32, 32)>>>(Wm, pbh, pbl, HIDD, N1);
    convW_kernel<<<dim3(HIDD / 32, K2D / 32), dim3(32, 32)>>>(Wo, pwh, pwl, K2D, HIDD);

    // 1) GEMM1 fused-chunk (R13) -> scan layout (+bias), unnormalized
    cudaFuncSetAttribute(gemm_fused_kernel<true, false, HIDD, N1>,
                         cudaFuncAttributeMaxDynamicSharedMemorySize, G_SMEM);
    gemm_fused_kernel<true, false, HIDD, N1>
        <<<dim3(N1 / 128, BT / 128), 256, G_SMEM>>>(pah, pal, pbh, pbl, bm, pm);

    // 2) Bidirectional scan v2 (cp.async smem ring) -> fp16 hi/lo
    scan_kernel<<<256, 32>>>(pm, pxh, pxl);

    // 3) GEMM2 fused-chunk (R13): out = gelu(x @ W_out + b_out)
    cudaFuncSetAttribute(gemm_fused_kernel<false, true, K2D, HIDD>,
                         cudaFuncAttributeMaxDynamicSharedMemorySize, G_SMEM);
    gemm_fused_kernel<false, true, K2D, HIDD>
        <<<dim3(HIDD / 128, BT / 128), 256, G_SMEM>>>(pxh, pxl, pwh, pwl, bo, out);
}

// round 16
// speedup vs baseline: 1.5637x; 1.0719x over previous
#include <cuda_runtime.h>
#include <cuda_fp16.h>
#include <cstdint>
#include <math.h>

// Problem constants
#define BB     8
#define TLEN   2048
#define HIDD   1024
#define NHH    16
#define MDD    16
#define BT     (BB * TLEN)          // 16384 rows
#define N1     (NHH * MDD * MDD)    // 4096
#define K2D    (NHH * MDD * 2)      // 512

// ---------------------------------------------------------------------------
// Scratch (device globals — no allocation allowed)
// ---------------------------------------------------------------------------
__device__ float  g_m[(size_t)BT * N1];               // scan layout [s][t][256] (UNNORMALIZED)
__device__ __half g_ah[(size_t)BT * HIDD];            // hs hi
__device__ __half g_al[(size_t)BT * HIDD];            // hs lo (unscaled)
__device__ __half g_bh[(size_t)N1 * HIDD];            // W_mat^T hi  [n][k]
__device__ __half g_bl[(size_t)N1 * HIDD];            // W_mat^T lo  [n][k]
__device__ __half g_xh[(size_t)BT * K2D];             // scan out hi
__device__ __half g_xl[(size_t)BT * K2D];             // scan out lo
__device__ __half g_wh[(size_t)HIDD * K2D];           // W_out^T hi [n][k]
__device__ __half g_wl[(size_t)HIDD * K2D];           // W_out^T lo [n][k]

// ---------------------------------------------------------------------------
// Helpers
// ---------------------------------------------------------------------------
__device__ __forceinline__ uint32_t smem_u32(const void* p) {
    uint32_t a;
    asm("{ .reg .u64 t; cvta.to.shared.u64 t, %1; cvt.u32.u64 %0, t; }" : "=r"(a) : "l"(p));
    return a;
}
#define CP_ASYNC16(dst, src) \
    asm volatile("cp.async.cg.shared.global [%0], [%1], 16;\n" :: "r"(dst), "l"(src) : "memory")
#define CP_COMMIT()  asm volatile("cp.async.commit_group;\n" ::: "memory")
#define CP_WAIT1()   asm volatile("cp.async.wait_group 1;\n" ::: "memory")
#define CP_WAIT11()  asm volatile("cp.async.wait_group 11;\n" ::: "memory")

__device__ __forceinline__ void ldsm_x4(uint32_t& r0, uint32_t& r1, uint32_t& r2,
                                        uint32_t& r3, uint32_t addr) {
    asm volatile("ldmatrix.sync.aligned.m8n8.x4.shared.b16 {%0,%1,%2,%3}, [%4];"
                 : "=r"(r0), "=r"(r1), "=r"(r2), "=r"(r3) : "r"(addr));
}
__device__ __forceinline__ void mma_f16(float* c, const uint32_t* a, const uint32_t* b) {
    asm volatile(
        "mma.sync.aligned.m16n8k16.row.col.f32.f16.f16.f32 "
        "{%0,%1,%2,%3}, {%4,%5,%6,%7}, {%8,%9}, {%0,%1,%2,%3};"
        : "+f"(c[0]), "+f"(c[1]), "+f"(c[2]), "+f"(c[3])
        : "r"(a[0]), "r"(a[1]), "r"(a[2]), "r"(a[3]), "r"(b[0]), "r"(b[1]));
}
__device__ __forceinline__ uint32_t swz64(uint32_t off) { return off ^ ((off >> 3) & 0x30); } // SW64

__device__ __forceinline__ void split_f16(float a, __half& h, __half& l) {
    h = __float2half_rn(a);
    l = __float2half_rn(a - __half2float(h));
}

// ---------------------------------------------------------------------------
// Conversion kernels
// ---------------------------------------------------------------------------
struct alignas(8) h4 { __half v[4]; };

__global__ __launch_bounds__(256)
void convA_kernel(const float* __restrict__ x, __half* __restrict__ hi,
                  __half* __restrict__ lo)
{
    const int i = blockIdx.x * blockDim.x + threadIdx.x;
    float4 v = ((const float4*)x)[i];
    h4 h, l;
    float a[4] = {v.x, v.y, v.z, v.w};
#pragma unroll
    for (int j = 0; j < 4; j++) split_f16(a[j], h.v[j], l.v[j]);
    ((h4*)hi)[i] = h;
    ((h4*)lo)[i] = l;
}

// Transpose W (KR x NC, row-major) -> [n][k] fp16 hi/lo
__global__ __launch_bounds__(1024)
void convW_kernel(const float* __restrict__ W, __half* __restrict__ wh,
                  __half* __restrict__ wl, int KR, int NC)
{
    __shared__ float tile[32][33];
    const int n_in = blockIdx.x * 32 + threadIdx.x;
    const int k_in = blockIdx.y * 32 + threadIdx.y;
    tile[threadIdx.y][threadIdx.x] = W[(size_t)k_in * NC + n_in];
    __syncthreads();
    const int n_out = blockIdx.x * 32 + threadIdx.y;
    const int k_out = blockIdx.y * 32 + threadIdx.x;
    const float v = tile[threadIdx.x][threadIdx.y];
    __half h, l;
    split_f16(v, h, l);
    const size_t o = (size_t)n_out * KR + k_out;
    wh[o] = h;
    wl[o] = l;
}

// ---------------------------------------------------------------------------
// FUSED-CHUNK HMMA GEMM (R13/R15 baseline — best known):
//   D = Ah*Bl + Al*Bh + Ah*Bh   [+ bias]
// CTA 128x128, 8 warps (2m x 4n), SW64 swizzle, 3-stage ring, 2 CTAs/SM.
// ---------------------------------------------------------------------------
#define CH_K     32                         // halfs per chunk
#define TILE_B   8192                       // 128 rows * 64 bytes
#define ST_B     (4 * TILE_B)               // 32KB per stage (Ah,Al,Bh,Bl)
#define G_SMEM   (1024 + 3 * ST_B)

template <bool PERM, bool GELU, int KDIM, int NDIM>
__global__ __launch_bounds__(256, 2)
void gemm_fused_kernel(const __half* __restrict__ Ah, const __half* __restrict__ Al,
                       const __half* __restrict__ Bh, const __half* __restrict__ Bl,
                       const float* __restrict__ bias, float* __restrict__ C)
{
    constexpr int NCHUNK = KDIM / CH_K;

    extern __shared__ char smem[];
    const uint32_t tiles = (smem_u32(smem) + 1023u) & ~1023u;
    const int tid = threadIdx.x;
    const int lane = tid & 31, warp = tid >> 5;
    const int wm = warp & 1, wn = warp >> 1;     // 2 x 4 warp grid
    const int bx = blockIdx.x;                   // N tile
    const int by = blockIdx.y;                   // M tile

    const int lr  = tid >> 2;          // 0..63 (row)
    const int lcb = (tid & 3) * 16;    // byte col within 64B row

    const __half* Asrcs[2] = {Ah, Al};
    const __half* Bsrcs[2] = {Bh, Bl};

    auto issue_loads = [&](int chunk) {
        const int stage = chunk % 3;
        const uint32_t s = tiles + stage * ST_B;
        const int koff = chunk * CH_K + (lcb >> 1);
#pragma unroll
        for (int a = 0; a < 2; a++) {
            const __half* Ap = Asrcs[a] + (size_t)(by * 128 + lr) * KDIM + koff;
            const uint32_t d = s + a * TILE_B;
            CP_ASYNC16(d + swz64(lr * 64 + lcb), Ap);
            CP_ASYNC16(d + swz64((lr + 64) * 64 + lcb), Ap + (size_t)64 * KDIM);
        }
#pragma unroll
        for (int b = 0; b < 2; b++) {
            const __half* Bp = Bsrcs[b] + (size_t)(bx * 128 + lr) * KDIM + koff;
            const uint32_t d = s + (2 + b) * TILE_B;
            CP_ASYNC16(d + swz64(lr * 64 + lcb), Bp);
            CP_ASYNC16(d + swz64((lr + 64) * 64 + lcb), Bp + (size_t)64 * KDIM);
        }
    };

    float acc[4][4][4];
#pragma unroll
    for (int i = 0; i < 4; i++)
#pragma unroll
        for (int j = 0; j < 4; j++)
#pragma unroll
            for (int k = 0; k < 4; k++) acc[i][j][k] = 0.0f;

    const int lrow = lane & 15;
    const int lkof = (lane >> 4) * 16;

    issue_loads(0); CP_COMMIT();
    issue_loads(1); CP_COMMIT();

    for (int i = 0; i < NCHUNK; i++) {
        CP_WAIT1();
        __syncthreads();
        if (i + 2 < NCHUNK) issue_loads(i + 2);
        CP_COMMIT();

        const uint32_t s   = tiles + (i % 3) * ST_B;
        const uint32_t a_h = s;
        const uint32_t a_l = s + TILE_B;
        const uint32_t b_h = s + 2 * TILE_B;
        const uint32_t b_l = s + 3 * TILE_B;

#pragma unroll
        for (int ks = 0; ks < 2; ks++) {
            const int kb = ks * 32 + lkof;

            uint32_t bhf[4][2], blf[4][2];
#pragma unroll
            for (int bt = 0; bt < 2; bt++) {
                const int row = wn * 32 + bt * 16 + lrow;
                uint32_t r0, r1, r2, r3;
                ldsm_x4(r0, r1, r2, r3, b_l + swz64(row * 64 + kb));
                blf[bt * 2 + 0][0] = r0; blf[bt * 2 + 1][0] = r1;
                blf[bt * 2 + 0][1] = r2; blf[bt * 2 + 1][1] = r3;
                ldsm_x4(r0, r1, r2, r3, b_h + swz64(row * 64 + kb));
                bhf[bt * 2 + 0][0] = r0; bhf[bt * 2 + 1][0] = r1;
                bhf[bt * 2 + 0][1] = r2; bhf[bt * 2 + 1][1] = r3;
            }

#pragma unroll
            for (int mt = 0; mt < 4; mt++) {
                const int row = wm * 64 + mt * 16 + lrow;
                uint32_t ahf[4], alf[4];
                ldsm_x4(ahf[0], ahf[1], ahf[2], ahf[3],
                        a_h + swz64(row * 64 + kb));
                ldsm_x4(alf[0], alf[1], alf[2], alf[3],
                        a_l + swz64(row * 64 + kb));
#pragma unroll
                for (int nt = 0; nt < 4; nt++)
                    mma_f16(acc[mt][nt], ahf, blf[nt]);
#pragma unroll
                for (int nt = 0; nt < 4; nt++)
                    mma_f16(acc[mt][nt], alf, bhf[nt]);
#pragma unroll
                for (int nt = 0; nt < 4; nt++)
                    mma_f16(acc[mt][nt], ahf, bhf[nt]);
            }
        }
    }

    // ---- epilogue ----
    const int g = lane >> 2, t4 = lane & 3;
#pragma unroll
    for (int mt = 0; mt < 4; mt++) {
#pragma unroll
        for (int nt = 0; nt < 4; nt++) {
            const int rm = by * 128 + wm * 64 + mt * 16 + g;
            const int cg = bx * 128 + wn * 32 + nt * 8 + t4 * 2;
            const float b0 = __ldg(&bias[cg]);
            const float b1 = __ldg(&bias[cg + 1]);
            float v0 = acc[mt][nt][0] + b0;
            float v1 = acc[mt][nt][1] + b1;
            float v2 = acc[mt][nt][2] + b0;
            float v3 = acc[mt][nt][3] + b1;
            if (GELU) {
                v0 = 0.5f * v0 * (1.0f + erff(v0 * 0.70710678118654752f));
                v1 = 0.5f * v1 * (1.0f + erff(v1 * 0.70710678118654752f));
                v2 = 0.5f * v2 * (1.0f + erff(v2 * 0.70710678118654752f));
                v3 = 0.5f * v3 * (1.0f + erff(v3 * 0.70710678118654752f));
            }
            if (PERM) {
                const int nh = cg >> 8, ij = cg & 255;
                const int b_ = rm >> 11, t_ = rm & (TLEN - 1);
                float* o = C + (((size_t)(b_ * 16 + nh) * TLEN + t_) * 256 + ij);
                *(float2*)o = make_float2(v0, v1);
                *(float2*)(o + 8 * 256) = make_float2(v2, v3);
            } else {
                float* o = C + ((size_t)rm * NDIM + cg);
                *(float2*)o = make_float2(v0, v1);
                *(float2*)(o + (size_t)8 * NDIM) = make_float2(v2, v3);
            }
        }
    }
}

// ---------------------------------------------------------------------------
// Scan v3: identical to v2 (cp.async smem ring, 12 slots, lane-local slices,
// pair-combine layout) EXCEPT the per-step normalization:
//   w = nv * rsqrtf(ss + 1e-12)
// replaces nv / (sqrtf(ss) + 1e-6). Without fast-math the old form lowered
// to IEEE sqrt + IEEE div subroutines (~150-250 issue cycles EVERY step) —
// with one warp per SMSP, that issue stream WAS the scan's 420 cyc/step.
// MUFU.RSQ + FMUL replaces it; the eps difference is <=1e-6 relative on w
// and GEMM2 is the last op, so the output shift is negligible.
// ---------------------------------------------------------------------------
#define SDEPTH 12

__global__ __launch_bounds__(32)
void scan_kernel(const float* __restrict__ mn, __half* __restrict__ xh,
                 __half* __restrict__ xl)
{
    __shared__ __align__(16) char ring[SDEPTH * 1024];

    const unsigned F = 0xffffffffu;
    const int lane = threadIdx.x & 31;
    const int s = blockIdx.x & 127;        // sequence (b*16+nh)
    const int d = blockIdx.x >> 7;         // 0 = lr, 1 = rl
    const int b = s >> 4;
    const int nh = s & 15;

    const uint32_t rb = smem_u32(ring);
    const uint32_t sw = (lane & 4) << 2;                 // 0 or 16
    const uint32_t o0 = ((uint32_t)lane * 32) ^ sw;
    const uint32_t o1 = ((uint32_t)lane * 32 + 16) ^ sw;

    const float* base = mn + (size_t)s * (TLEN * 256) + lane * 8;

    const int t0 = d ? (TLEN - 1) : 0;
    const int dt = d ? -1 : 1;

    // lane l: row = l>>1, column half h = l&1 (cols h*8 .. h*8+7)
    const int h16 = (lane & 1) << 4;

    float u = (lane < 2) ? 1.0f : 0.0f;    // v0 = e0, row 0 pair
    const size_t xoff = (size_t)b * TLEN * 512 + nh * 32 + d * 16 + (lane >> 1);

    // prologue: fill 12 slots (one commit group each)
#pragma unroll
    for (int j = 0; j < SDEPTH; j++) {
        const float* q = base + (size_t)(t0 + j * dt) * 256;
        CP_ASYNC16(rb + j * 1024 + o0, q);
        CP_ASYNC16(rb + j * 1024 + o1, q + 4);
        CP_COMMIT();
    }

    int slot = 0;
#pragma unroll 1
    for (int blk = 0; blk < TLEN / 4; ++blk) {
#pragma unroll
        for (int sub = 0; sub < 4; ++sub) {
            const int step = blk * 4 + sub;
            const int t = t0 + step * dt;

            CP_WAIT11();                       // slot's group complete

            const float4 c0 = *(const float4*)(ring + slot * 1024 + o0);
            const float4 c1 = *(const float4*)(ring + slot * 1024 + o1);

            // prefetch step+SDEPTH into this slot (clamped near the end)
            int tp = t + SDEPTH * dt;
            tp = tp < 0 ? 0 : (tp > TLEN - 1 ? TLEN - 1 : tp);
            const float* q = base + (size_t)tp * 256;
            CP_ASYNC16(rb + slot * 1024 + o0, q);
            CP_ASYNC16(rb + slot * 1024 + o1, q + 4);
            CP_COMMIT();

            // broadcast v[h*8 + k] (v[c] lives in lanes 2c, 2c+1)
            const float vb0 = __shfl_sync(F, u, h16 + 0);
            const float vb1 = __shfl_sync(F, u, h16 + 2);
            const float vb2 = __shfl_sync(F, u, h16 + 4);
            const float vb3 = __shfl_sync(F, u, h16 + 6);
            const float vb4 = __shfl_sync(F, u, h16 + 8);
            const float vb5 = __shfl_sync(F, u, h16 + 10);
            const float vb6 = __shfl_sync(F, u, h16 + 12);
            const float vb7 = __shfl_sync(F, u, h16 + 14);

            float pA = c0.x * vb0;
            pA = fmaf(c0.y, vb1, pA);
            pA = fmaf(c0.z, vb2, pA);
            pA = fmaf(c0.w, vb3, pA);
            float pB = c1.x * vb4;
            pB = fmaf(c1.y, vb5, pB);
            pB = fmaf(c1.z, vb6, pB);
            pB = fmaf(c1.w, vb7, pB);
            const float pp = pA + pB;

            // combine column halves (lanes 2r, 2r+1 both get row r's nv)
            const float nv = pp + __shfl_xor_sync(F, pp, 1);

            // squared norm over the 16 distinct rows
            float ss = nv * nv;
            ss += __shfl_xor_sync(F, ss, 2);
            ss += __shfl_xor_sync(F, ss, 4);
            ss += __shfl_xor_sync(F, ss, 8);
            ss += __shfl_xor_sync(F, ss, 16);
            // single MUFU.RSQ + FMUL (was IEEE sqrt + IEEE div subroutines)
            const float w = nv * rsqrtf(ss + 1e-12f);

            if ((lane & 1) == 0) {
                __half h, l;
                split_f16(w, h, l);
                xh[xoff + (size_t)t * 512] = h;
                xl[xoff + (size_t)t * 512] = l;
            }

            // rescale every 4th step; other steps carry unnormalized nv
            u = (sub == 3) ? w : nv;

            if (++slot == SDEPTH) slot = 0;
        }
    }
}

// ---------------------------------------------------------------------------
// Launch
// ---------------------------------------------------------------------------
extern "C" void kernel_launch(void* const* d_in, const int* in_sizes, int n_in,
                              void* d_out, int out_size)
{
    const float* hs = (const float*)d_in[0];
    const float* Wm = (const float*)d_in[1];
    const float* bm = (const float*)d_in[2];
    const float* Wo = (const float*)d_in[3];
    const float* bo = (const float*)d_in[4];
    float* out = (float*)d_out;

    float* pm;
    __half *pah, *pal, *pbh, *pbl, *pxh, *pxl, *pwh, *pwl;
    cudaGetSymbolAddress((void**)&pm, g_m);
    cudaGetSymbolAddress((void**)&pah, g_ah);
    cudaGetSymbolAddress((void**)&pal, g_al);
    cudaGetSymbolAddress((void**)&pbh, g_bh);
    cudaGetSymbolAddress((void**)&pbl, g_bl);
    cudaGetSymbolAddress((void**)&pxh, g_xh);
    cudaGetSymbolAddress((void**)&pxl, g_xl);
    cudaGetSymbolAddress((void**)&pwh, g_wh);
    cudaGetSymbolAddress((void**)&pwl, g_wl);

    // 0) fp16 splits
    convA_kernel<<<(BT * HIDD / 4) / 256, 256>>>(hs, pah, pal);
    convW_kernel<<<dim3(N1 / 32, HIDD / 32), dim3(32, 32)>>>(Wm, pbh, pbl, HIDD, N1);
    convW_kernel<<<dim3(HIDD / 32, K2D / 32), dim3(32, 32)>>>(Wo, pwh, pwl, K2D, HIDD);

    // 1) GEMM1 fused-chunk -> scan layout (+bias), unnormalized
    cudaFuncSetAttribute(gemm_fused_kernel<true, false, HIDD, N1>,
                         cudaFuncAttributeMaxDynamicSharedMemorySize, G_SMEM);
    gemm_fused_kernel<true, false, HIDD, N1>
        <<<dim3(N1 / 128, BT / 128), 256, G_SMEM>>>(pah, pal, pbh, pbl, bm, pm);

    // 2) Bidirectional scan v3 (rsqrt normalization) -> fp16 hi/lo
    scan_kernel<<<256, 32>>>(pm, pxh, pxl);

    // 3) GEMM2 fused-chunk: out = gelu(x @ W_out + b_out)
    cudaFuncSetAttribute(gemm_fused_kernel<false, true, K2D, HIDD>,
                         cudaFuncAttributeMaxDynamicSharedMemorySize, G_SMEM);
    gemm_fused_kernel<false, true, K2D, HIDD>
        <<<dim3(HIDD / 128, BT / 128), 256, G_SMEM>>>(pxh, pxl, pwh, pwl, bo, out);
}